// round 12
// baseline (speedup 1.0000x reference)
#include <cuda_runtime.h>
#include <math.h>

// Problem dims (fixed by the reference setup_inputs)
#define BSZ    8192
#define DDIM   1024
#define D2     512
#define NH     2048
#define FSTEPS 8

// Scratch (allocation-free rule: __device__ globals)
__device__ float  g_h1[(size_t)BSZ * NH];   // 64 MB
__device__ float  g_h2[(size_t)BSZ * NH];   // 64 MB
__device__ float  g_z0[(size_t)BSZ * DDIM]; // 32 MB
__device__ float  g_z1[(size_t)BSZ * DDIM]; // 32 MB
__device__ double g_partial[1024];

__device__ __forceinline__ float lrelu(float x) {
    // jax.nn.leaky_relu default slope 0.01
    return fmaxf(x, 0.01f * x);
}

__device__ __forceinline__ float logsigf(float x) {
    // matches jax: min(x,0) - log1p(exp(-|x|))
    if (x >= 0.0f) return -log1pf(expf(-x));
    return x - log1pf(expf(x));
}

// ---------------------------------------------------------------------------
// SGEMM: C(M=8192 x Nn) = A(M x K, row stride lda) * Bw(K x Nn, row-major)
// EPI==0: C[r][n] = lrelu(acc + bias[n])
// EPI==1: coupling epilogue:
//   t  = acc + bias[n]                  (n in [0, 512))
//   yb = Zin[r][512+n] + rint(t)
//   Zout[r][511-n]  = yb                (reversed concat)
//   Zout[r][1023-n] = Zin[r][n]
// Tiling: 128x128 block, BK=8, 256 threads, 8x8 per thread, double-buffered.
// ---------------------------------------------------------------------------
template <int EPI>
__global__ __launch_bounds__(256)
void sgemm_kernel(const float* __restrict__ A, int lda,
                  const float* __restrict__ Bw,
                  const float* __restrict__ bias,
                  float* __restrict__ C,
                  const float* __restrict__ Zin,
                  float* __restrict__ Zout,
                  int Nn, int K)
{
    const int BM = 128, BN = 128, BK = 8;
    __shared__ float As[2][BK][BM];   // transposed A tile
    __shared__ float Bs[2][BK][BN];

    const int tid = threadIdx.x;
    const int bx = blockIdx.x;  // N tile
    const int by = blockIdx.y;  // M tile

    // global->shared load mapping (one float4 each for A and B per k-tile)
    const int aRow = tid >> 1;           // 0..127
    const int aCol = (tid & 1) << 2;     // 0 or 4  (k offset)
    const int bRow = tid >> 5;           // 0..7    (k offset)
    const int bCol = (tid & 31) << 2;    // 0..124

    const float* Aptr = A  + (size_t)(by * BM + aRow) * lda + aCol;
    const float* Bptr = Bw + (size_t)bRow * Nn + (size_t)bx * BN + bCol;

    // compute mapping: 4+4 split in both dims for conflict-free LDS.128
    const int tr = tid >> 4;   // 0..15
    const int tc = tid & 15;   // 0..15

    float acc[8][8];
#pragma unroll
    for (int i = 0; i < 8; ++i)
#pragma unroll
        for (int j = 0; j < 8; ++j) acc[i][j] = 0.0f;

    // prologue: tile 0 into buf 0
    {
        float4 a4 = *(const float4*)Aptr;
        As[0][aCol + 0][aRow] = a4.x;
        As[0][aCol + 1][aRow] = a4.y;
        As[0][aCol + 2][aRow] = a4.z;
        As[0][aCol + 3][aRow] = a4.w;
        float4 b4 = *(const float4*)Bptr;
        *(float4*)&Bs[0][bRow][bCol] = b4;
    }
    __syncthreads();

    const int KT = K / BK;
    int buf = 0;

    for (int kt = 0; kt < KT; ++kt) {
        float4 na, nb;
        if (kt + 1 < KT) {
            na = *(const float4*)(Aptr + (kt + 1) * BK);
            nb = *(const float4*)(Bptr + (size_t)(kt + 1) * BK * Nn);
        }

#pragma unroll
        for (int k = 0; k < BK; ++k) {
            float4 a0 = *(const float4*)&As[buf][k][tr * 4];
            float4 a1 = *(const float4*)&As[buf][k][64 + tr * 4];
            float4 b0 = *(const float4*)&Bs[buf][k][tc * 4];
            float4 b1 = *(const float4*)&Bs[buf][k][64 + tc * 4];
            float rm[8] = {a0.x, a0.y, a0.z, a0.w, a1.x, a1.y, a1.z, a1.w};
            float rn[8] = {b0.x, b0.y, b0.z, b0.w, b1.x, b1.y, b1.z, b1.w};
#pragma unroll
            for (int i = 0; i < 8; ++i)
#pragma unroll
                for (int j = 0; j < 8; ++j)
                    acc[i][j] = fmaf(rm[i], rn[j], acc[i][j]);
        }

        if (kt + 1 < KT) {
            As[buf ^ 1][aCol + 0][aRow] = na.x;
            As[buf ^ 1][aCol + 1][aRow] = na.y;
            As[buf ^ 1][aCol + 2][aRow] = na.z;
            As[buf ^ 1][aCol + 3][aRow] = na.w;
            *(float4*)&Bs[buf ^ 1][bRow][bCol] = nb;
            __syncthreads();
            buf ^= 1;
        }
    }

    // epilogue
#pragma unroll
    for (int i = 0; i < 8; ++i) {
        const int lr = (i < 4) ? (tr * 4 + i) : (64 + tr * 4 + (i - 4));
        const int r  = by * BM + lr;
#pragma unroll
        for (int j = 0; j < 8; ++j) {
            const int lc = (j < 4) ? (tc * 4 + j) : (64 + tc * 4 + (j - 4));
            const int n  = bx * BN + lc;
            if (EPI == 0) {
                C[(size_t)r * Nn + n] = lrelu(acc[i][j] + bias[n]);
            } else {
                const float t  = acc[i][j] + bias[n];
                const float xa = Zin[(size_t)r * DDIM + n];
                const float xb = Zin[(size_t)r * DDIM + D2 + n];
                const float yb = xb + rintf(t);   // rint = half-to-even = jnp.round
                Zout[(size_t)r * DDIM + (D2 - 1 - n)]   = yb;
                Zout[(size_t)r * DDIM + (DDIM - 1 - n)] = xa;
            }
        }
    }
}

// ---------------------------------------------------------------------------
// Per-block deterministic partial sums of log_p over 8 rows each.
// ---------------------------------------------------------------------------
__global__ __launch_bounds__(256)
void logp_kernel(const float* __restrict__ Z,
                 const float* __restrict__ mean,
                 const float* __restrict__ logscale)
{
    __shared__ double sred[256];
    const int b   = blockIdx.x;        // 0..1023, 8 rows each
    const int tid = threadIdx.x;
    const size_t base = (size_t)b * 8 * DDIM;

    double s = 0.0;
    for (int idx = tid; idx < 8 * DDIM; idx += 256) {
        const int d = idx & (DDIM - 1);
        const float z  = Z[base + idx];
        const float sc = expf(logscale[d]);
        const float m  = mean[d];
        const float u  = (z + 0.5f - m) / sc;
        const float v  = (z - 0.5f - m) / sc;
        const float la = logsigf(u);
        const float lb = logsigf(v);
        const float lp = la + logf(1.0f - expf(lb - la) + 1e-8f);
        s += (double)lp;
    }
    sred[tid] = s;
    __syncthreads();
#pragma unroll
    for (int off = 128; off > 0; off >>= 1) {
        if (tid < off) sred[tid] += sred[tid + off];
        __syncthreads();
    }
    if (tid == 0) g_partial[b] = sred[0];
}

__global__ __launch_bounds__(256)
void finalize_kernel(float* __restrict__ out)
{
    __shared__ double sred[256];
    const int tid = threadIdx.x;
    double s = 0.0;
    for (int i = tid; i < 1024; i += 256) s += g_partial[i];
    sred[tid] = s;
    __syncthreads();
#pragma unroll
    for (int off = 128; off > 0; off >>= 1) {
        if (tid < off) sred[tid] += sred[tid + off];
        __syncthreads();
    }
    if (tid == 0) out[0] = (float)(-sred[0] / (double)BSZ);
}

// ---------------------------------------------------------------------------
extern "C" void kernel_launch(void* const* d_in, const int* in_sizes, int n_in,
                              void* d_out, int out_size)
{
    const float* x        = (const float*)d_in[0];
    const float* W1       = (const float*)d_in[1];
    const float* b1       = (const float*)d_in[2];
    const float* W2       = (const float*)d_in[3];
    const float* b2       = (const float*)d_in[4];
    const float* W3       = (const float*)d_in[5];
    const float* b3       = (const float*)d_in[6];
    const float* mean     = (const float*)d_in[7];
    const float* logscale = (const float*)d_in[8];

    float *h1, *h2, *z0, *z1;
    cudaGetSymbolAddress((void**)&h1, g_h1);
    cudaGetSymbolAddress((void**)&h2, g_h2);
    cudaGetSymbolAddress((void**)&z0, g_z0);
    cudaGetSymbolAddress((void**)&z1, g_z1);

    const dim3 block(256);
    const dim3 grid12(NH / 128, BSZ / 128);  // (16, 64)
    const dim3 grid3 (D2 / 128, BSZ / 128);  // (4, 64)

    for (int f = 0; f < FSTEPS; ++f) {
        const float* zin  = (f == 0) ? x : ((f & 1) ? z0 : z1);
        float*       zout = (f & 1) ? z1 : z0;

        const float* W1f = W1 + (size_t)f * D2 * NH;
        const float* b1f = b1 + (size_t)f * NH;
        const float* W2f = W2 + (size_t)f * NH * NH;
        const float* b2f = b2 + (size_t)f * NH;
        const float* W3f = W3 + (size_t)f * NH * D2;
        const float* b3f = b3 + (size_t)f * D2;

        // h1 = lrelu(xa @ W1 + b1)    xa = zin[:, :512] (row stride 1024)
        sgemm_kernel<0><<<grid12, block>>>(zin, DDIM, W1f, b1f, h1,
                                           nullptr, nullptr, NH, D2);
        // h2 = lrelu(h1 @ W2 + b2)
        sgemm_kernel<0><<<grid12, block>>>(h1, NH, W2f, b2f, h2,
                                           nullptr, nullptr, NH, NH);
        // t = h2 @ W3 + b3 ; coupling + reversal fused
        sgemm_kernel<1><<<grid3, block>>>(h2, NH, W3f, b3f, nullptr,
                                          zin, zout, D2, NH);
    }

    // after 8 steps final z is in z1
    logp_kernel<<<1024, block>>>(z1, mean, logscale);
    finalize_kernel<<<1, block>>>((float*)d_out);
}

// round 14
// speedup vs baseline: 2.6539x; 2.6539x over previous
#include <cuda_runtime.h>
#include <cuda_bf16.h>
#include <math.h>
#include <stdint.h>

#define BSZ    8192
#define DDIM   1024
#define D2     512
#define NH     2048
#define FSTEPS 8

// ---------------- scratch (__device__ globals; allocation-free rule) -------
__device__ __nv_bfloat16 g_xb[(size_t)BSZ * DDIM];    // x as bf16 (exact ints)
__device__ __nv_bfloat16 g_z0[(size_t)BSZ * DDIM];
__device__ __nv_bfloat16 g_z1[(size_t)BSZ * DDIM];
__device__ __nv_bfloat16 g_h1h[(size_t)BSZ * NH];
__device__ __nv_bfloat16 g_h1l[(size_t)BSZ * NH];
__device__ __nv_bfloat16 g_h2h[(size_t)BSZ * NH];
__device__ __nv_bfloat16 g_h2l[(size_t)BSZ * NH];
__device__ double g_partial[1024];
// transposed + split weights: Bt[f][n][k] (bf16 hi / lo)
__device__ __nv_bfloat16 g_w1_hi[(size_t)FSTEPS * NH * D2];
__device__ __nv_bfloat16 g_w1_lo[(size_t)FSTEPS * NH * D2];
__device__ __nv_bfloat16 g_w2_hi[(size_t)FSTEPS * NH * NH];
__device__ __nv_bfloat16 g_w2_lo[(size_t)FSTEPS * NH * NH];
__device__ __nv_bfloat16 g_w3_hi[(size_t)FSTEPS * D2 * NH];
__device__ __nv_bfloat16 g_w3_lo[(size_t)FSTEPS * D2 * NH];

// ---------------- helpers ---------------------------------------------------
__device__ __forceinline__ float lrelu(float x) { return fmaxf(x, 0.01f * x); }

__device__ __forceinline__ float logsigf(float x) {
    if (x >= 0.0f) return -log1pf(expf(-x));
    return x - log1pf(expf(x));
}

__device__ __forceinline__ uint32_t smem_u32(const void* p) {
    uint32_t a;
    asm("{ .reg .u64 t; cvta.to.shared.u64 t, %1; cvt.u32.u64 %0, t; }"
        : "=r"(a) : "l"(p));
    return a;
}

#define CP_ASYNC16(s, g) \
    asm volatile("cp.async.cg.shared.global [%0], [%1], 16;" :: "r"(s), "l"(g) : "memory")
#define CP_COMMIT() asm volatile("cp.async.commit_group;" ::: "memory")
#define CP_WAIT(N)  asm volatile("cp.async.wait_group %0;" :: "n"(N) : "memory")

#define LDSM4(r0, r1, r2, r3, addr) \
    asm volatile("ldmatrix.sync.aligned.m8n8.x4.shared.b16 {%0,%1,%2,%3}, [%4];" \
        : "=r"(r0), "=r"(r1), "=r"(r2), "=r"(r3) : "r"(addr))

#define MMA16816(c, a, b0, b1) \
    asm volatile("mma.sync.aligned.m16n8k16.row.col.f32.bf16.bf16.f32 " \
        "{%0,%1,%2,%3}, {%4,%5,%6,%7}, {%8,%9}, {%0,%1,%2,%3};" \
        : "+f"((c)[0]), "+f"((c)[1]), "+f"((c)[2]), "+f"((c)[3]) \
        : "r"((a)[0]), "r"((a)[1]), "r"((a)[2]), "r"((a)[3]), "r"(b0), "r"(b1))

// ---------------- weight transpose + bf16 hi/lo split -----------------------
// W[f][K][Nn] (row-major) -> Bt_hi/lo[f][Nn][K]
__global__ __launch_bounds__(1024)
void convW_kernel(const float* __restrict__ W,
                  __nv_bfloat16* __restrict__ Bhi,
                  __nv_bfloat16* __restrict__ Blo,
                  int K, int Nn)
{
    __shared__ float t[32][33];
    const int f = blockIdx.z;
    const float* Wf = W + (size_t)f * K * Nn;
    __nv_bfloat16* Hf = Bhi + (size_t)f * K * Nn;
    __nv_bfloat16* Lf = Blo + (size_t)f * K * Nn;
    const int tx = threadIdx.x, ty = threadIdx.y;
    const int k0 = blockIdx.y * 32, n0 = blockIdx.x * 32;
    t[ty][tx] = Wf[(size_t)(k0 + ty) * Nn + n0 + tx];
    __syncthreads();
    const float v = t[tx][ty];
    const __nv_bfloat16 hi = __float2bfloat16(v);
    const __nv_bfloat16 lo = __float2bfloat16(v - __bfloat162float(hi));
    Hf[(size_t)(n0 + ty) * K + k0 + tx] = hi;
    Lf[(size_t)(n0 + ty) * K + k0 + tx] = lo;
}

// x fp32 (integers) -> bf16 (exact)
__global__ __launch_bounds__(256)
void convX_kernel(const float* __restrict__ x, __nv_bfloat16* __restrict__ o)
{
    const int i = blockIdx.x * 256 + threadIdx.x;   // i indexes float4
    const float4 v = ((const float4*)x)[i];
    ((__nv_bfloat162*)o)[i * 2 + 0] =
        __halves2bfloat162(__float2bfloat16(v.x), __float2bfloat16(v.y));
    ((__nv_bfloat162*)o)[i * 2 + 1] =
        __halves2bfloat162(__float2bfloat16(v.z), __float2bfloat16(v.w));
}

// ---------------- warp-mma GEMM ---------------------------------------------
// D[128x128] = A(bf16 hi[/lo], M x K, stride lda) * Bt(bf16 hi/lo, [Nn][K])^T
// TERMS==2: D = A*Bhi + A*Blo          (A exact, GEMM1)
// TERMS==3: D = Ahi*Bhi + Ahi*Blo + Alo*Bhi
// EPI 0: h = lrelu(acc + bias[n]); write split bf16 hi/lo to Chi/Clo
// EPI 1: coupling epilogue (bias + rint + reversal) on bf16 z buffers
static constexpr int STG        = 65536;           // 4 x 16KB tiles per stage
static constexpr int SMEM_DYN   = 2 * STG;

template <int EPI, int TERMS>
__global__ __launch_bounds__(256, 1)
void mma_gemm(const __nv_bfloat16* __restrict__ Ahi_g,
              const __nv_bfloat16* __restrict__ Alo_g,
              int lda,
              const __nv_bfloat16* __restrict__ Bhi_g,
              const __nv_bfloat16* __restrict__ Blo_g,
              const float* __restrict__ bias,
              __nv_bfloat16* __restrict__ Chi,
              __nv_bfloat16* __restrict__ Clo,
              const __nv_bfloat16* __restrict__ Zin,
              __nv_bfloat16* __restrict__ Zout,
              int Nn, int K)
{
    extern __shared__ char smem[];
    __shared__ float sbias[128];

    const uint32_t sbase = smem_u32(smem);
    const int tid = threadIdx.x;
    const int wid = tid >> 5, lid = tid & 31;
    const int bx = blockIdx.x, by = blockIdx.y;
    const int warp_m = wid & 1;     // rows warp_m*64 .. +63
    const int warp_n = wid >> 1;    // cols warp_n*32 .. +31

    if (tid < 128) sbias[tid] = bias[bx * 128 + tid];

    const __nv_bfloat16* Ahi = Ahi_g + (size_t)(by * 128) * lda;
    const __nv_bfloat16* Alo = (TERMS == 3) ? (Alo_g + (size_t)(by * 128) * lda) : nullptr;
    const __nv_bfloat16* Bhi = Bhi_g + (size_t)(bx * 128) * K;
    const __nv_bfloat16* Blo = Blo_g + (size_t)(bx * 128) * K;

    const int KT = K >> 6;

    // --- tile loader: 128 rows x 64 bf16, XOR-swizzled 16B units ---
    auto load_tile = [&](uint32_t soff, const __nv_bfloat16* g, int ld, int kc) {
#pragma unroll
        for (int i = 0; i < 4; ++i) {
            const int idx = (i << 8) + tid;          // 0..1023
            const int row = idx >> 3, u = idx & 7;
            const uint32_t s = sbase + soff + row * 128 + ((u ^ (row & 7)) << 4);
            const __nv_bfloat16* gp = g + (size_t)row * ld + kc + (u << 3);
            CP_ASYNC16(s, gp);
        }
    };
    auto load_stage = [&](int st, int kt) {
        const int kc = kt << 6;
        const uint32_t so = (uint32_t)st * STG;
        load_tile(so + 0,     Ahi, lda, kc);
        if (TERMS == 3) load_tile(so + 16384, Alo, lda, kc);
        load_tile(so + 32768, Bhi, K, kc);
        load_tile(so + 49152, Blo, K, kc);
        CP_COMMIT();
    };

    // --- per-lane ldmatrix address pieces ---
    const int rsub  = lid & 7;
    const int a_roff = rsub + (((lid >> 3) & 1) << 3);
    const int a_ub   = (lid >> 4) & 1;
    const int b_roff = rsub + (((lid >> 4) & 1) << 3);
    const int b_ub   = (lid >> 3) & 1;

    int aRowB[4], aSw7[4];
#pragma unroll
    for (int mt = 0; mt < 4; ++mt) {
        const int r = warp_m * 64 + mt * 16 + a_roff;
        aRowB[mt] = r * 128; aSw7[mt] = r & 7;
    }
    int bRowB[2], bSw7[2];
#pragma unroll
    for (int ng = 0; ng < 2; ++ng) {
        const int r = warp_n * 32 + ng * 16 + b_roff;
        bRowB[ng] = r * 128; bSw7[ng] = r & 7;
    }

    float acc[4][4][4];
#pragma unroll
    for (int mt = 0; mt < 4; ++mt)
#pragma unroll
        for (int nt = 0; nt < 4; ++nt)
#pragma unroll
            for (int q = 0; q < 4; ++q) acc[mt][nt][q] = 0.0f;

    // --- pipeline ---
    load_stage(0, 0);
    load_stage(1, 1);

    for (int kt = 0; kt < KT; ++kt) {
        if (kt + 1 < KT) { CP_WAIT(1); } else { CP_WAIT(0); }
        __syncthreads();

        const uint32_t so = sbase + (uint32_t)(kt & 1) * STG;
#pragma unroll
        for (int kk = 0; kk < 4; ++kk) {
            uint32_t ah[4][4], al[4][4];
#pragma unroll
            for (int mt = 0; mt < 4; ++mt) {
                const int u = (kk << 1) + a_ub;
                const uint32_t ad = so + aRowB[mt] + ((u ^ aSw7[mt]) << 4);
                LDSM4(ah[mt][0], ah[mt][1], ah[mt][2], ah[mt][3], ad);
                if (TERMS == 3) {
                    LDSM4(al[mt][0], al[mt][1], al[mt][2], al[mt][3], ad + 16384);
                }
            }
            uint32_t bh[2][4], bl[2][4];
#pragma unroll
            for (int ng = 0; ng < 2; ++ng) {
                const int u = (kk << 1) + b_ub;
                const uint32_t bd = so + 32768 + bRowB[ng] + ((u ^ bSw7[ng]) << 4);
                LDSM4(bh[ng][0], bh[ng][1], bh[ng][2], bh[ng][3], bd);
                LDSM4(bl[ng][0], bl[ng][1], bl[ng][2], bl[ng][3], bd + 16384);
            }
#pragma unroll
            for (int mt = 0; mt < 4; ++mt)
#pragma unroll
                for (int nt = 0; nt < 4; ++nt) {
                    const int ng = nt >> 1, h = (nt & 1) << 1;
                    MMA16816(acc[mt][nt], ah[mt], bh[ng][h], bh[ng][h + 1]);
                    MMA16816(acc[mt][nt], ah[mt], bl[ng][h], bl[ng][h + 1]);
                    if (TERMS == 3)
                        MMA16816(acc[mt][nt], al[mt], bh[ng][h], bh[ng][h + 1]);
                }
        }
        __syncthreads();
        if (kt + 2 < KT) load_stage(kt & 1, kt + 2);
    }

    // --- epilogue ---
    const int quad = lid >> 2, t4 = lid & 3;
#pragma unroll
    for (int mt = 0; mt < 4; ++mt) {
        const int r0 = by * 128 + warp_m * 64 + mt * 16 + quad;
#pragma unroll
        for (int nt = 0; nt < 4; ++nt) {
            const int lc = warp_n * 32 + nt * 8 + t4 * 2;
            const int gc = bx * 128 + lc;
            const float* a = acc[mt][nt];
            if (EPI == 0) {
#pragma unroll
                for (int rr = 0; rr < 2; ++rr) {
                    const float v0 = lrelu(a[rr * 2 + 0] + sbias[lc]);
                    const float v1 = lrelu(a[rr * 2 + 1] + sbias[lc + 1]);
                    const __nv_bfloat16 h0 = __float2bfloat16(v0);
                    const __nv_bfloat16 h1 = __float2bfloat16(v1);
                    const __nv_bfloat16 l0 = __float2bfloat16(v0 - __bfloat162float(h0));
                    const __nv_bfloat16 l1 = __float2bfloat16(v1 - __bfloat162float(h1));
                    const size_t off = (size_t)(r0 + rr * 8) * Nn + gc;
                    *(__nv_bfloat162*)(Chi + off) = __halves2bfloat162(h0, h1);
                    *(__nv_bfloat162*)(Clo + off) = __halves2bfloat162(l0, l1);
                }
            } else {
#pragma unroll
                for (int rr = 0; rr < 2; ++rr) {
                    const int r = r0 + rr * 8;
                    const size_t zr = (size_t)r * DDIM;
                    const int n = gc;   // 0..510, even
                    const __nv_bfloat162 xa2 = *(const __nv_bfloat162*)(Zin + zr + n);
                    const __nv_bfloat162 xb2 = *(const __nv_bfloat162*)(Zin + zr + D2 + n);
                    const float t0 = a[rr * 2 + 0] + sbias[lc];
                    const float t1 = a[rr * 2 + 1] + sbias[lc + 1];
                    const float yb0 = __bfloat162float(xb2.x) + rintf(t0);
                    const float yb1 = __bfloat162float(xb2.y) + rintf(t1);
                    // reversed: index D2-1-n holds yb(n); pack pairs descending
                    *(__nv_bfloat162*)(Zout + zr + (D2 - 2 - n)) =
                        __halves2bfloat162(__float2bfloat16(yb1), __float2bfloat16(yb0));
                    *(__nv_bfloat162*)(Zout + zr + (DDIM - 2 - n)) =
                        __halves2bfloat162(xa2.y, xa2.x);
                }
            }
        }
    }
}

// ---------------- final log-prob reduction ----------------------------------
__global__ __launch_bounds__(256)
void logp_kernel(const __nv_bfloat16* __restrict__ Z,
                 const float* __restrict__ mean,
                 const float* __restrict__ logscale)
{
    __shared__ double sred[256];
    const int b   = blockIdx.x;
    const int tid = threadIdx.x;
    const size_t base = (size_t)b * 8 * DDIM;

    double s = 0.0;
    for (int idx = tid; idx < 8 * DDIM; idx += 256) {
        const int d = idx & (DDIM - 1);
        const float z  = __bfloat162float(Z[base + idx]);
        const float sc = expf(logscale[d]);
        const float m  = mean[d];
        const float la = logsigf((z + 0.5f - m) / sc);
        const float lb = logsigf((z - 0.5f - m) / sc);
        const float lp = la + logf(1.0f - expf(lb - la) + 1e-8f);
        s += (double)lp;
    }
    sred[tid] = s;
    __syncthreads();
#pragma unroll
    for (int off = 128; off > 0; off >>= 1) {
        if (tid < off) sred[tid] += sred[tid + off];
        __syncthreads();
    }
    if (tid == 0) g_partial[b] = sred[0];
}

__global__ __launch_bounds__(256)
void finalize_kernel(float* __restrict__ out)
{
    __shared__ double sred[256];
    const int tid = threadIdx.x;
    double s = 0.0;
    for (int i = tid; i < 1024; i += 256) s += g_partial[i];
    sred[tid] = s;
    __syncthreads();
#pragma unroll
    for (int off = 128; off > 0; off >>= 1) {
        if (tid < off) sred[tid] += sred[tid + off];
        __syncthreads();
    }
    if (tid == 0) out[0] = (float)(-sred[0] / (double)BSZ);
}

// ---------------------------------------------------------------------------
extern "C" void kernel_launch(void* const* d_in, const int* in_sizes, int n_in,
                              void* d_out, int out_size)
{
    const float* x        = (const float*)d_in[0];
    const float* W1       = (const float*)d_in[1];
    const float* b1       = (const float*)d_in[2];
    const float* W2       = (const float*)d_in[3];
    const float* b2       = (const float*)d_in[4];
    const float* W3       = (const float*)d_in[5];
    const float* b3       = (const float*)d_in[6];
    const float* mean     = (const float*)d_in[7];
    const float* logscale = (const float*)d_in[8];

    __nv_bfloat16 *xb, *z0, *z1, *h1h, *h1l, *h2h, *h2l;
    cudaGetSymbolAddress((void**)&xb,  g_xb);
    cudaGetSymbolAddress((void**)&z0,  g_z0);
    cudaGetSymbolAddress((void**)&z1,  g_z1);
    cudaGetSymbolAddress((void**)&h1h, g_h1h);
    cudaGetSymbolAddress((void**)&h1l, g_h1l);
    cudaGetSymbolAddress((void**)&h2h, g_h2h);
    cudaGetSymbolAddress((void**)&h2l, g_h2l);
    __nv_bfloat16 *w1h, *w1l, *w2h, *w2l, *w3h, *w3l;
    cudaGetSymbolAddress((void**)&w1h, g_w1_hi);
    cudaGetSymbolAddress((void**)&w1l, g_w1_lo);
    cudaGetSymbolAddress((void**)&w2h, g_w2_hi);
    cudaGetSymbolAddress((void**)&w2l, g_w2_lo);
    cudaGetSymbolAddress((void**)&w3h, g_w3_hi);
    cudaGetSymbolAddress((void**)&w3l, g_w3_lo);

    cudaFuncSetAttribute(mma_gemm<0, 2>, cudaFuncAttributeMaxDynamicSharedMemorySize, SMEM_DYN);
    cudaFuncSetAttribute(mma_gemm<0, 3>, cudaFuncAttributeMaxDynamicSharedMemorySize, SMEM_DYN);
    cudaFuncSetAttribute(mma_gemm<1, 3>, cudaFuncAttributeMaxDynamicSharedMemorySize, SMEM_DYN);

    // weight transpose + bf16 split, all steps
    convW_kernel<<<dim3(NH / 32, D2 / 32, FSTEPS), dim3(32, 32)>>>(W1, w1h, w1l, D2, NH);
    convW_kernel<<<dim3(NH / 32, NH / 32, FSTEPS), dim3(32, 32)>>>(W2, w2h, w2l, NH, NH);
    convW_kernel<<<dim3(D2 / 32, NH / 32, FSTEPS), dim3(32, 32)>>>(W3, w3h, w3l, NH, D2);
    convX_kernel<<<(BSZ * DDIM / 4) / 256, 256>>>(x, xb);

    const dim3 block(256);
    const dim3 grid12(NH / 128, BSZ / 128);   // (16, 64)
    const dim3 grid3 (D2 / 128, BSZ / 128);   // (4, 64)

    for (int f = 0; f < FSTEPS; ++f) {
        const __nv_bfloat16* zin = (f == 0) ? xb : ((f & 1) ? z0 : z1);
        __nv_bfloat16* zout = (f & 1) ? z1 : z0;

        const __nv_bfloat16* w1hf = w1h + (size_t)f * NH * D2;
        const __nv_bfloat16* w1lf = w1l + (size_t)f * NH * D2;
        const __nv_bfloat16* w2hf = w2h + (size_t)f * NH * NH;
        const __nv_bfloat16* w2lf = w2l + (size_t)f * NH * NH;
        const __nv_bfloat16* w3hf = w3h + (size_t)f * D2 * NH;
        const __nv_bfloat16* w3lf = w3l + (size_t)f * D2 * NH;
        const float* b1f = b1 + (size_t)f * NH;
        const float* b2f = b2 + (size_t)f * NH;
        const float* b3f = b3 + (size_t)f * D2;

        // h1 = lrelu(xa @ W1 + b1); A = z (exact bf16) -> 2 terms
        mma_gemm<0, 2><<<grid12, block, SMEM_DYN>>>(zin, nullptr, DDIM,
                                                    w1hf, w1lf, b1f,
                                                    h1h, h1l, nullptr, nullptr, NH, D2);
        // h2 = lrelu(h1 @ W2 + b2); 3 terms
        mma_gemm<0, 3><<<grid12, block, SMEM_DYN>>>(h1h, h1l, NH,
                                                    w2hf, w2lf, b2f,
                                                    h2h, h2l, nullptr, nullptr, NH, NH);
        // t = h2 @ W3 + b3; coupling + reversal fused; 3 terms
        mma_gemm<1, 3><<<grid3, block, SMEM_DYN>>>(h2h, h2l, NH,
                                                   w3hf, w3lf, b3f,
                                                   nullptr, nullptr, zin, zout, D2, NH);
    }

    logp_kernel<<<1024, block>>>(z1, mean, logscale);
    finalize_kernel<<<1, block>>>((float*)d_out);
}

// round 15
// speedup vs baseline: 2.7209x; 1.0252x over previous
#include <cuda_runtime.h>
#include <cuda_bf16.h>
#include <math.h>
#include <stdint.h>

#define BSZ    8192
#define DDIM   1024
#define D2     512
#define NH     2048
#define FSTEPS 8

// ---------------- scratch (__device__ globals; allocation-free rule) -------
__device__ __nv_bfloat16 g_xb[(size_t)BSZ * DDIM];    // x as bf16 (exact ints)
__device__ __nv_bfloat16 g_z0[(size_t)BSZ * DDIM];
__device__ __nv_bfloat16 g_z1[(size_t)BSZ * DDIM];
__device__ __nv_bfloat16 g_h1h[(size_t)BSZ * NH];
__device__ __nv_bfloat16 g_h1l[(size_t)BSZ * NH];
__device__ __nv_bfloat16 g_h2h[(size_t)BSZ * NH];
__device__ __nv_bfloat16 g_h2l[(size_t)BSZ * NH];
__device__ double g_partial[1024];
// transposed + split weights: Bt[f][n][k] (bf16 hi / lo)
__device__ __nv_bfloat16 g_w1_hi[(size_t)FSTEPS * NH * D2];
__device__ __nv_bfloat16 g_w1_lo[(size_t)FSTEPS * NH * D2];
__device__ __nv_bfloat16 g_w2_hi[(size_t)FSTEPS * NH * NH];
__device__ __nv_bfloat16 g_w2_lo[(size_t)FSTEPS * NH * NH];
__device__ __nv_bfloat16 g_w3_hi[(size_t)FSTEPS * D2 * NH];
__device__ __nv_bfloat16 g_w3_lo[(size_t)FSTEPS * D2 * NH];

// ---------------- helpers ---------------------------------------------------
__device__ __forceinline__ float lrelu(float x) { return fmaxf(x, 0.01f * x); }

__device__ __forceinline__ float logsigf(float x) {
    if (x >= 0.0f) return -log1pf(expf(-x));
    return x - log1pf(expf(x));
}

__device__ __forceinline__ uint32_t smem_u32(const void* p) {
    uint32_t a;
    asm("{ .reg .u64 t; cvta.to.shared.u64 t, %1; cvt.u32.u64 %0, t; }"
        : "=r"(a) : "l"(p));
    return a;
}

#define CP_ASYNC16(s, g) \
    asm volatile("cp.async.cg.shared.global [%0], [%1], 16;" :: "r"(s), "l"(g) : "memory")
#define CP_COMMIT() asm volatile("cp.async.commit_group;" ::: "memory")
#define CP_WAIT(N)  asm volatile("cp.async.wait_group %0;" :: "n"(N) : "memory")

#define LDSM4(r0, r1, r2, r3, addr) \
    asm volatile("ldmatrix.sync.aligned.m8n8.x4.shared.b16 {%0,%1,%2,%3}, [%4];" \
        : "=r"(r0), "=r"(r1), "=r"(r2), "=r"(r3) : "r"(addr))

#define MMA16816(c, a, b0, b1) \
    asm volatile("mma.sync.aligned.m16n8k16.row.col.f32.bf16.bf16.f32 " \
        "{%0,%1,%2,%3}, {%4,%5,%6,%7}, {%8,%9}, {%0,%1,%2,%3};" \
        : "+f"((c)[0]), "+f"((c)[1]), "+f"((c)[2]), "+f"((c)[3]) \
        : "r"((a)[0]), "r"((a)[1]), "r"((a)[2]), "r"((a)[3]), "r"(b0), "r"(b1))

// ---------------- weight transpose + bf16 hi/lo split -----------------------
// W[f][K][Nn] (row-major) -> Bt_hi/lo[f][Nn][K]
__global__ __launch_bounds__(1024)
void convW_kernel(const float* __restrict__ W,
                  __nv_bfloat16* __restrict__ Bhi,
                  __nv_bfloat16* __restrict__ Blo,
                  int K, int Nn)
{
    __shared__ float t[32][33];
    const int f = blockIdx.z;
    const float* Wf = W + (size_t)f * K * Nn;
    __nv_bfloat16* Hf = Bhi + (size_t)f * K * Nn;
    __nv_bfloat16* Lf = Blo + (size_t)f * K * Nn;
    const int tx = threadIdx.x, ty = threadIdx.y;
    const int k0 = blockIdx.y * 32, n0 = blockIdx.x * 32;
    t[ty][tx] = Wf[(size_t)(k0 + ty) * Nn + n0 + tx];
    __syncthreads();
    const float v = t[tx][ty];
    const __nv_bfloat16 hi = __float2bfloat16(v);
    const __nv_bfloat16 lo = __float2bfloat16(v - __bfloat162float(hi));
    Hf[(size_t)(n0 + ty) * K + k0 + tx] = hi;
    Lf[(size_t)(n0 + ty) * K + k0 + tx] = lo;
}

// x fp32 (integers) -> bf16 (exact)
__global__ __launch_bounds__(256)
void convX_kernel(const float* __restrict__ x, __nv_bfloat16* __restrict__ o)
{
    const int i = blockIdx.x * 256 + threadIdx.x;   // i indexes float4
    const float4 v = ((const float4*)x)[i];
    ((__nv_bfloat162*)o)[i * 2 + 0] =
        __halves2bfloat162(__float2bfloat16(v.x), __float2bfloat16(v.y));
    ((__nv_bfloat162*)o)[i * 2 + 1] =
        __halves2bfloat162(__float2bfloat16(v.z), __float2bfloat16(v.w));
}

// ---------------- warp-mma GEMM ---------------------------------------------
// D[128x128] = A(bf16 hi[/lo], M x K, stride lda) * Bt(bf16 hi/lo, [Nn][K])^T
// TERMS==2: D = A*Bhi + A*Blo          (A exact, GEMM1)
// TERMS==3: D = Ahi*Bhi + Ahi*Blo + Alo*Bhi
// EPI 0: h = lrelu(acc + bias[n]); write split bf16 hi/lo to Chi/Clo
// EPI 1: coupling epilogue (bias + rint + reversal) on bf16 z buffers
// 3-stage cp.async pipeline, ONE __syncthreads per k-chunk.
template <int TERMS> struct StageCfg;
template <> struct StageCfg<2> {
    static constexpr int OB_HI = 16384, OB_LO = 32768, BYTES = 49152;
};
template <> struct StageCfg<3> {
    static constexpr int OB_HI = 32768, OB_LO = 49152, BYTES = 65536;
};

template <int EPI, int TERMS>
__global__ __launch_bounds__(256, 1)
void mma_gemm(const __nv_bfloat16* __restrict__ Ahi_g,
              const __nv_bfloat16* __restrict__ Alo_g,
              int lda,
              const __nv_bfloat16* __restrict__ Bhi_g,
              const __nv_bfloat16* __restrict__ Blo_g,
              const float* __restrict__ bias,
              __nv_bfloat16* __restrict__ Chi,
              __nv_bfloat16* __restrict__ Clo,
              const __nv_bfloat16* __restrict__ Zin,
              __nv_bfloat16* __restrict__ Zout,
              int Nn, int K)
{
    constexpr int STG   = StageCfg<TERMS>::BYTES;
    constexpr int OB_HI = StageCfg<TERMS>::OB_HI;

    extern __shared__ char smem[];
    __shared__ float sbias[128];

    const uint32_t sbase = smem_u32(smem);
    const int tid = threadIdx.x;
    const int wid = tid >> 5, lid = tid & 31;
    const int bx = blockIdx.x, by = blockIdx.y;
    const int warp_m = wid & 1;     // rows warp_m*64 .. +63
    const int warp_n = wid >> 1;    // cols warp_n*32 .. +31

    if (tid < 128) sbias[tid] = bias[bx * 128 + tid];

    const __nv_bfloat16* Ahi = Ahi_g + (size_t)(by * 128) * lda;
    const __nv_bfloat16* Alo = (TERMS == 3) ? (Alo_g + (size_t)(by * 128) * lda) : nullptr;
    const __nv_bfloat16* Bhi = Bhi_g + (size_t)(bx * 128) * K;
    const __nv_bfloat16* Blo = Blo_g + (size_t)(bx * 128) * K;

    const int KT = K >> 6;

    // --- tile loader: 128 rows x 64 bf16, XOR-swizzled 16B units ---
    auto load_tile = [&](uint32_t soff, const __nv_bfloat16* g, int ld, int kc) {
#pragma unroll
        for (int i = 0; i < 4; ++i) {
            const int idx = (i << 8) + tid;          // 0..1023
            const int row = idx >> 3, u = idx & 7;
            const uint32_t s = sbase + soff + row * 128 + ((u ^ (row & 7)) << 4);
            const __nv_bfloat16* gp = g + (size_t)row * ld + kc + (u << 3);
            CP_ASYNC16(s, gp);
        }
    };
    auto load_stage = [&](int st, int kt) {
        const int kc = kt << 6;
        const uint32_t so = (uint32_t)st * STG;
        load_tile(so + 0, Ahi, lda, kc);
        if (TERMS == 3) load_tile(so + 16384, Alo, lda, kc);
        load_tile(so + OB_HI,         Bhi, K, kc);
        load_tile(so + OB_HI + 16384, Blo, K, kc);
        CP_COMMIT();
    };

    // --- per-lane ldmatrix address pieces ---
    const int rsub  = lid & 7;
    const int a_roff = rsub + (((lid >> 3) & 1) << 3);
    const int a_ub   = (lid >> 4) & 1;
    const int b_roff = rsub + (((lid >> 4) & 1) << 3);
    const int b_ub   = (lid >> 3) & 1;

    int aRowB[4], aSw7[4];
#pragma unroll
    for (int mt = 0; mt < 4; ++mt) {
        const int r = warp_m * 64 + mt * 16 + a_roff;
        aRowB[mt] = r * 128; aSw7[mt] = r & 7;
    }
    int bRowB[2], bSw7[2];
#pragma unroll
    for (int ng = 0; ng < 2; ++ng) {
        const int r = warp_n * 32 + ng * 16 + b_roff;
        bRowB[ng] = r * 128; bSw7[ng] = r & 7;
    }

    float acc[4][4][4];
#pragma unroll
    for (int mt = 0; mt < 4; ++mt)
#pragma unroll
        for (int nt = 0; nt < 4; ++nt)
#pragma unroll
            for (int q = 0; q < 4; ++q) acc[mt][nt][q] = 0.0f;

    // --- 3-stage pipeline, one barrier per chunk ---
    load_stage(0, 0);
    load_stage(1, 1);

    int slot = 0;          // slot of chunk kt (cycles 0,1,2)
    int wslot = 2;         // slot for chunk kt+2
    for (int kt = 0; kt < KT; ++kt) {
        // stage kt landed when <=1 newer group outstanding (groups retire in order)
        if (kt < KT - 1) { CP_WAIT(1); } else { CP_WAIT(0); }
        __syncthreads();   // publish stage kt; proves slot(kt-1)==wslot is drained

        if (kt + 2 < KT) load_stage(wslot, kt + 2);

        const uint32_t so = sbase + (uint32_t)slot * STG;
#pragma unroll
        for (int kk = 0; kk < 4; ++kk) {
            uint32_t ah[4][4], al[4][4];
#pragma unroll
            for (int mt = 0; mt < 4; ++mt) {
                const int u = (kk << 1) + a_ub;
                const uint32_t ad = so + aRowB[mt] + ((u ^ aSw7[mt]) << 4);
                LDSM4(ah[mt][0], ah[mt][1], ah[mt][2], ah[mt][3], ad);
                if (TERMS == 3) {
                    LDSM4(al[mt][0], al[mt][1], al[mt][2], al[mt][3], ad + 16384);
                }
            }
            uint32_t bh[2][4], bl[2][4];
#pragma unroll
            for (int ng = 0; ng < 2; ++ng) {
                const int u = (kk << 1) + b_ub;
                const uint32_t bd = so + OB_HI + bRowB[ng] + ((u ^ bSw7[ng]) << 4);
                LDSM4(bh[ng][0], bh[ng][1], bh[ng][2], bh[ng][3], bd);
                LDSM4(bl[ng][0], bl[ng][1], bl[ng][2], bl[ng][3], bd + 16384);
            }
#pragma unroll
            for (int mt = 0; mt < 4; ++mt)
#pragma unroll
                for (int nt = 0; nt < 4; ++nt) {
                    const int ng = nt >> 1, h = (nt & 1) << 1;
                    MMA16816(acc[mt][nt], ah[mt], bh[ng][h], bh[ng][h + 1]);
                    MMA16816(acc[mt][nt], ah[mt], bl[ng][h], bl[ng][h + 1]);
                    if (TERMS == 3)
                        MMA16816(acc[mt][nt], al[mt], bh[ng][h], bh[ng][h + 1]);
                }
        }

        slot  = (slot == 2)  ? 0 : slot + 1;
        wslot = (wslot == 2) ? 0 : wslot + 1;
    }

    // --- epilogue ---
    const int quad = lid >> 2, t4 = lid & 3;
#pragma unroll
    for (int mt = 0; mt < 4; ++mt) {
        const int r0 = by * 128 + warp_m * 64 + mt * 16 + quad;
#pragma unroll
        for (int nt = 0; nt < 4; ++nt) {
            const int lc = warp_n * 32 + nt * 8 + t4 * 2;
            const int gc = bx * 128 + lc;
            const float* a = acc[mt][nt];
            if (EPI == 0) {
#pragma unroll
                for (int rr = 0; rr < 2; ++rr) {
                    const float v0 = lrelu(a[rr * 2 + 0] + sbias[lc]);
                    const float v1 = lrelu(a[rr * 2 + 1] + sbias[lc + 1]);
                    const __nv_bfloat16 h0 = __float2bfloat16(v0);
                    const __nv_bfloat16 h1 = __float2bfloat16(v1);
                    const __nv_bfloat16 l0 = __float2bfloat16(v0 - __bfloat162float(h0));
                    const __nv_bfloat16 l1 = __float2bfloat16(v1 - __bfloat162float(h1));
                    const size_t off = (size_t)(r0 + rr * 8) * Nn + gc;
                    *(__nv_bfloat162*)(Chi + off) = __halves2bfloat162(h0, h1);
                    *(__nv_bfloat162*)(Clo + off) = __halves2bfloat162(l0, l1);
                }
            } else {
#pragma unroll
                for (int rr = 0; rr < 2; ++rr) {
                    const int r = r0 + rr * 8;
                    const size_t zr = (size_t)r * DDIM;
                    const int n = gc;   // 0..510, even
                    const __nv_bfloat162 xa2 = *(const __nv_bfloat162*)(Zin + zr + n);
                    const __nv_bfloat162 xb2 = *(const __nv_bfloat162*)(Zin + zr + D2 + n);
                    const float t0 = a[rr * 2 + 0] + sbias[lc];
                    const float t1 = a[rr * 2 + 1] + sbias[lc + 1];
                    const float yb0 = __bfloat162float(xb2.x) + rintf(t0);
                    const float yb1 = __bfloat162float(xb2.y) + rintf(t1);
                    // reversed: index D2-1-n holds yb(n); pack pairs descending
                    *(__nv_bfloat162*)(Zout + zr + (D2 - 2 - n)) =
                        __halves2bfloat162(__float2bfloat16(yb1), __float2bfloat16(yb0));
                    *(__nv_bfloat162*)(Zout + zr + (DDIM - 2 - n)) =
                        __halves2bfloat162(xa2.y, xa2.x);
                }
            }
        }
    }
}

// ---------------- final log-prob reduction ----------------------------------
__global__ __launch_bounds__(256)
void logp_kernel(const __nv_bfloat16* __restrict__ Z,
                 const float* __restrict__ mean,
                 const float* __restrict__ logscale)
{
    __shared__ double sred[256];
    const int b   = blockIdx.x;
    const int tid = threadIdx.x;
    const size_t base = (size_t)b * 8 * DDIM;

    double s = 0.0;
    for (int idx = tid; idx < 8 * DDIM; idx += 256) {
        const int d = idx & (DDIM - 1);
        const float z  = __bfloat162float(Z[base + idx]);
        const float sc = expf(logscale[d]);
        const float m  = mean[d];
        const float la = logsigf((z + 0.5f - m) / sc);
        const float lb = logsigf((z - 0.5f - m) / sc);
        const float lp = la + logf(1.0f - expf(lb - la) + 1e-8f);
        s += (double)lp;
    }
    sred[tid] = s;
    __syncthreads();
#pragma unroll
    for (int off = 128; off > 0; off >>= 1) {
        if (tid < off) sred[tid] += sred[tid + off];
        __syncthreads();
    }
    if (tid == 0) g_partial[b] = sred[0];
}

__global__ __launch_bounds__(256)
void finalize_kernel(float* __restrict__ out)
{
    __shared__ double sred[256];
    const int tid = threadIdx.x;
    double s = 0.0;
    for (int i = tid; i < 1024; i += 256) s += g_partial[i];
    sred[tid] = s;
    __syncthreads();
#pragma unroll
    for (int off = 128; off > 0; off >>= 1) {
        if (tid < off) sred[tid] += sred[tid + off];
        __syncthreads();
    }
    if (tid == 0) out[0] = (float)(-sred[0] / (double)BSZ);
}

// ---------------------------------------------------------------------------
extern "C" void kernel_launch(void* const* d_in, const int* in_sizes, int n_in,
                              void* d_out, int out_size)
{
    const float* x        = (const float*)d_in[0];
    const float* W1       = (const float*)d_in[1];
    const float* b1       = (const float*)d_in[2];
    const float* W2       = (const float*)d_in[3];
    const float* b2       = (const float*)d_in[4];
    const float* W3       = (const float*)d_in[5];
    const float* b3       = (const float*)d_in[6];
    const float* mean     = (const float*)d_in[7];
    const float* logscale = (const float*)d_in[8];

    __nv_bfloat16 *xb, *z0, *z1, *h1h, *h1l, *h2h, *h2l;
    cudaGetSymbolAddress((void**)&xb,  g_xb);
    cudaGetSymbolAddress((void**)&z0,  g_z0);
    cudaGetSymbolAddress((void**)&z1,  g_z1);
    cudaGetSymbolAddress((void**)&h1h, g_h1h);
    cudaGetSymbolAddress((void**)&h1l, g_h1l);
    cudaGetSymbolAddress((void**)&h2h, g_h2h);
    cudaGetSymbolAddress((void**)&h2l, g_h2l);
    __nv_bfloat16 *w1h, *w1l, *w2h, *w2l, *w3h, *w3l;
    cudaGetSymbolAddress((void**)&w1h, g_w1_hi);
    cudaGetSymbolAddress((void**)&w1l, g_w1_lo);
    cudaGetSymbolAddress((void**)&w2h, g_w2_hi);
    cudaGetSymbolAddress((void**)&w2l, g_w2_lo);
    cudaGetSymbolAddress((void**)&w3h, g_w3_hi);
    cudaGetSymbolAddress((void**)&w3l, g_w3_lo);

    const int SMEM2 = 3 * StageCfg<2>::BYTES;   // 144 KB
    const int SMEM3 = 3 * StageCfg<3>::BYTES;   // 192 KB
    cudaFuncSetAttribute(mma_gemm<0, 2>, cudaFuncAttributeMaxDynamicSharedMemorySize, SMEM2);
    cudaFuncSetAttribute(mma_gemm<0, 3>, cudaFuncAttributeMaxDynamicSharedMemorySize, SMEM3);
    cudaFuncSetAttribute(mma_gemm<1, 3>, cudaFuncAttributeMaxDynamicSharedMemorySize, SMEM3);

    // weight transpose + bf16 split, all steps
    convW_kernel<<<dim3(NH / 32, D2 / 32, FSTEPS), dim3(32, 32)>>>(W1, w1h, w1l, D2, NH);
    convW_kernel<<<dim3(NH / 32, NH / 32, FSTEPS), dim3(32, 32)>>>(W2, w2h, w2l, NH, NH);
    convW_kernel<<<dim3(D2 / 32, NH / 32, FSTEPS), dim3(32, 32)>>>(W3, w3h, w3l, NH, D2);
    convX_kernel<<<(BSZ * DDIM / 4) / 256, 256>>>(x, xb);

    const dim3 block(256);
    const dim3 grid12(NH / 128, BSZ / 128);   // (16, 64)
    const dim3 grid3 (D2 / 128, BSZ / 128);   // (4, 64)

    for (int f = 0; f < FSTEPS; ++f) {
        const __nv_bfloat16* zin = (f == 0) ? xb : ((f & 1) ? z0 : z1);
        __nv_bfloat16* zout = (f & 1) ? z1 : z0;

        const __nv_bfloat16* w1hf = w1h + (size_t)f * NH * D2;
        const __nv_bfloat16* w1lf = w1l + (size_t)f * NH * D2;
        const __nv_bfloat16* w2hf = w2h + (size_t)f * NH * NH;
        const __nv_bfloat16* w2lf = w2l + (size_t)f * NH * NH;
        const __nv_bfloat16* w3hf = w3h + (size_t)f * D2 * NH;
        const __nv_bfloat16* w3lf = w3l + (size_t)f * D2 * NH;
        const float* b1f = b1 + (size_t)f * NH;
        const float* b2f = b2 + (size_t)f * NH;
        const float* b3f = b3 + (size_t)f * D2;

        // h1 = lrelu(xa @ W1 + b1); A = z (exact bf16) -> 2 terms
        mma_gemm<0, 2><<<grid12, block, SMEM2>>>(zin, nullptr, DDIM,
                                                 w1hf, w1lf, b1f,
                                                 h1h, h1l, nullptr, nullptr, NH, D2);
        // h2 = lrelu(h1 @ W2 + b2); 3 terms
        mma_gemm<0, 3><<<grid12, block, SMEM3>>>(h1h, h1l, NH,
                                                 w2hf, w2lf, b2f,
                                                 h2h, h2l, nullptr, nullptr, NH, NH);
        // t = h2 @ W3 + b3; coupling + reversal fused; 3 terms
        mma_gemm<1, 3><<<grid3, block, SMEM3>>>(h2h, h2l, NH,
                                                w3hf, w3lf, b3f,
                                                nullptr, nullptr, zin, zout, D2, NH);
    }

    logp_kernel<<<1024, block>>>(z1, mean, logscale);
    finalize_kernel<<<1, block>>>((float*)d_out);
}